// round 1
// baseline (speedup 1.0000x reference)
#include <cuda_runtime.h>
#include <cuda_fp16.h>
#include <cstdint>

#define NH 16
#define HD 64
#define DIM 1024
#define BB 4
#define NN 2048
#define KK 2048
#define QSCALE 0.125f

// ---------------- scratch (device globals: allocation-free) ----------------
__device__ float g_ctxn[(size_t)BB * KK * DIM];       // 32 MB
__device__ float g_q   [(size_t)BB * NN * DIM];       // 32 MB (pre-scaled by QSCALE)
__device__ float g_kv  [(size_t)BB * KK * 2 * DIM];   // 64 MB (k | v per row)
__device__ float g_att [(size_t)BB * NN * DIM];       // 32 MB

// ---------------- helpers ----------------
__device__ __forceinline__ float tf32r(float x) {
    asm("cvt.rna.tf32.f32 %0, %1;" : "=f"(x) : "f"(x));
    return x;
}

__device__ __forceinline__ void mma_tf32(float c[4], const float a[4], const float b[2]) {
    asm volatile(
        "mma.sync.aligned.m16n8k8.row.col.f32.tf32.tf32.f32 "
        "{%0,%1,%2,%3},{%4,%5,%6,%7},{%8,%9},{%0,%1,%2,%3};\n"
        : "+f"(c[0]), "+f"(c[1]), "+f"(c[2]), "+f"(c[3])
        : "r"(__float_as_uint(a[0])), "r"(__float_as_uint(a[1])),
          "r"(__float_as_uint(a[2])), "r"(__float_as_uint(a[3])),
          "r"(__float_as_uint(b[0])), "r"(__float_as_uint(b[1])));
}

__device__ __forceinline__ void mma_f16(float c[4], const unsigned a[4], const unsigned b[2]) {
    asm volatile(
        "mma.sync.aligned.m16n8k16.row.col.f32.f16.f16.f32 "
        "{%0,%1,%2,%3},{%4,%5,%6,%7},{%8,%9},{%0,%1,%2,%3};\n"
        : "+f"(c[0]), "+f"(c[1]), "+f"(c[2]), "+f"(c[3])
        : "r"(a[0]), "r"(a[1]), "r"(a[2]), "r"(a[3]),
          "r"(b[0]), "r"(b[1]));
}

__device__ __forceinline__ unsigned pack_h2(float a, float b) {
    __half2 h = __floats2half2_rn(a, b);
    return *reinterpret_cast<unsigned*>(&h);
}

// ---------------- rmsnorm: one block per row of 1024 ----------------
__global__ void rmsnorm_kernel(const float* __restrict__ in, float* __restrict__ out) {
    const int row = blockIdx.x;
    const int tid = threadIdx.x;  // 256 threads, 4 floats each
    const float4 v = reinterpret_cast<const float4*>(in + (size_t)row * DIM)[tid];
    float ss = v.x * v.x + v.y * v.y + v.z * v.z + v.w * v.w;
    #pragma unroll
    for (int o = 16; o; o >>= 1) ss += __shfl_xor_sync(0xffffffffu, ss, o);
    __shared__ float part[8];
    __shared__ float tot;
    if ((tid & 31) == 0) part[tid >> 5] = ss;
    __syncthreads();
    if (tid == 0) {
        float s = 0.f;
        #pragma unroll
        for (int i = 0; i < 8; i++) s += part[i];
        tot = s;
    }
    __syncthreads();
    const float r = rsqrtf(tot * (1.0f / DIM) + 1e-6f);
    float4 o4 = make_float4(v.x * r, v.y * r, v.z * r, v.w * r);
    reinterpret_cast<float4*>(out + (size_t)row * DIM)[tid] = o4;
}

// ---------------- generic tf32 GEMM: C = alpha*(A @ W + bias) ----------------
// A: [M,Kd] row-major fp32, W: [Kd,N] row-major fp32, bias: [N]
// block tile 128x128, k-tile 32, 256 threads = 8 warps (2m x 4n), warp tile 64x32
#define GSTR 136
__global__ void gemm_tf32(const float* __restrict__ A, const float* __restrict__ W,
                          const float* __restrict__ bias, float* __restrict__ C,
                          int M, int N, int Kd, float alpha) {
    __shared__ float As[32][GSTR];  // As[k][m]
    __shared__ float Bs[32][GSTR];  // Bs[k][n]
    const int tid = threadIdx.x;
    const int lane = tid & 31, wid = tid >> 5;
    const int g = lane >> 2, t = lane & 3;
    const int bm = blockIdx.y * 128, bn = blockIdx.x * 128;
    const int wm = (wid >> 2) * 64, wn = (wid & 3) * 32;

    float acc[4][4][4];
    #pragma unroll
    for (int i = 0; i < 4; i++)
        #pragma unroll
        for (int j = 0; j < 4; j++)
            #pragma unroll
            for (int r = 0; r < 4; r++) acc[i][j][r] = 0.f;

    const int amr = tid >> 3;        // 0..31 (A row within tile, +32*i)
    const int ak4 = (tid & 7) * 4;   // A k offset
    const int bkr = tid >> 5;        // 0..7 (B k row, +8*i)
    const int bn4 = (tid & 31) * 4;  // B n offset

    float4 ar[4], br[4];
    auto loadg = [&](int k0) {
        #pragma unroll
        for (int i = 0; i < 4; i++)
            ar[i] = *reinterpret_cast<const float4*>(&A[(size_t)(bm + amr + i * 32) * Kd + k0 + ak4]);
        #pragma unroll
        for (int i = 0; i < 4; i++)
            br[i] = *reinterpret_cast<const float4*>(&W[(size_t)(k0 + bkr + i * 8) * N + bn + bn4]);
    };
    auto stores = [&]() {
        #pragma unroll
        for (int i = 0; i < 4; i++) {
            As[ak4 + 0][amr + i * 32] = tf32r(ar[i].x);
            As[ak4 + 1][amr + i * 32] = tf32r(ar[i].y);
            As[ak4 + 2][amr + i * 32] = tf32r(ar[i].z);
            As[ak4 + 3][amr + i * 32] = tf32r(ar[i].w);
            float4 cb = make_float4(tf32r(br[i].x), tf32r(br[i].y), tf32r(br[i].z), tf32r(br[i].w));
            *reinterpret_cast<float4*>(&Bs[bkr + i * 8][bn4]) = cb;
        }
    };

    const int NK = Kd / 32;
    loadg(0);
    stores();
    __syncthreads();
    for (int kt = 0; kt < NK; kt++) {
        if (kt + 1 < NK) loadg((kt + 1) * 32);
        #pragma unroll
        for (int kk = 0; kk < 32; kk += 8) {
            float af[4][4], bf[4][2];
            #pragma unroll
            for (int mt = 0; mt < 4; mt++) {
                const int m0 = wm + mt * 16 + g;
                af[mt][0] = As[kk + t][m0];
                af[mt][1] = As[kk + t][m0 + 8];
                af[mt][2] = As[kk + 4 + t][m0];
                af[mt][3] = As[kk + 4 + t][m0 + 8];
            }
            #pragma unroll
            for (int nt = 0; nt < 4; nt++) {
                const int n0 = wn + nt * 8 + g;
                bf[nt][0] = Bs[kk + t][n0];
                bf[nt][1] = Bs[kk + 4 + t][n0];
            }
            #pragma unroll
            for (int mt = 0; mt < 4; mt++)
                #pragma unroll
                for (int nt = 0; nt < 4; nt++)
                    mma_tf32(acc[mt][nt], af[mt], bf[nt]);
        }
        __syncthreads();
        if (kt + 1 < NK) {
            stores();
            __syncthreads();
        }
    }

    #pragma unroll
    for (int mt = 0; mt < 4; mt++) {
        const int r0 = bm + wm + mt * 16 + g;
        #pragma unroll
        for (int nt = 0; nt < 4; nt++) {
            const int c0 = bn + wn + nt * 8 + 2 * t;
            const float b0 = bias[c0], b1 = bias[c0 + 1];
            float2 v0 = make_float2(alpha * (acc[mt][nt][0] + b0), alpha * (acc[mt][nt][1] + b1));
            float2 v1 = make_float2(alpha * (acc[mt][nt][2] + b0), alpha * (acc[mt][nt][3] + b1));
            *reinterpret_cast<float2*>(&C[(size_t)r0 * N + c0]) = v0;
            *reinterpret_cast<float2*>(&C[(size_t)(r0 + 8) * N + c0]) = v1;
        }
    }
}

// ---------------- fused attention ----------------
// Clip to [-10,10] bounds exp => no running max needed. One pass:
//   O += exp(clip(Q K^T)) @ V ; rowsum accumulated ; divide at end.
// grid: (N/128, B*H), 256 threads (8 warps x 16 q-rows). K/V tiled 64 keys.
#define KSTR 68
#define VSTR 72
__global__ void attn_kernel(const float* __restrict__ q, const float* __restrict__ kv,
                            float* __restrict__ att) {
    __shared__ float Ks[64][KSTR];     // Ks[kpos][d]   (tf32)
    __shared__ __half Vs[64][VSTR];    // Vs[d][kpos]   (transposed, fp16)
    const int tid = threadIdx.x, lane = tid & 31, wid = tid >> 5;
    const int g = lane >> 2, t = lane & 3;
    const int bh = blockIdx.y, b = bh >> 4, h = bh & 15;
    const int r0 = blockIdx.x * 128 + wid * 16 + g;
    const float* qb = q + (size_t)b * NN * DIM + h * HD;
    const float* kvb = kv + (size_t)b * KK * 2 * DIM + h * HD;

    // resident Q fragments: 16 rows x 64 d per warp, tf32 m16n8k8 A-layout
    float qf[8][4];
    #pragma unroll
    for (int c = 0; c < 8; c++) {
        qf[c][0] = tf32r(qb[(size_t)r0 * DIM + c * 8 + t]);
        qf[c][1] = tf32r(qb[(size_t)(r0 + 8) * DIM + c * 8 + t]);
        qf[c][2] = tf32r(qb[(size_t)r0 * DIM + c * 8 + 4 + t]);
        qf[c][3] = tf32r(qb[(size_t)(r0 + 8) * DIM + c * 8 + 4 + t]);
    }

    float o[8][4];
    #pragma unroll
    for (int i = 0; i < 8; i++)
        #pragma unroll
        for (int r = 0; r < 4; r++) o[i][r] = 0.f;
    float rs0 = 0.f, rs1 = 0.f;

    const int kp = tid >> 2;  // 0..63 (key row this thread loads)
    for (int kc = 0; kc < KK; kc += 64) {
        __syncthreads();
        #pragma unroll
        for (int jj = 0; jj < 4; jj++) {
            const int c4 = ((tid & 3) + jj * 4) * 4;
            float4 kk4 = *reinterpret_cast<const float4*>(&kvb[(size_t)(kc + kp) * (2 * DIM) + c4]);
            Ks[kp][c4 + 0] = tf32r(kk4.x);
            Ks[kp][c4 + 1] = tf32r(kk4.y);
            Ks[kp][c4 + 2] = tf32r(kk4.z);
            Ks[kp][c4 + 3] = tf32r(kk4.w);
            float4 vv4 = *reinterpret_cast<const float4*>(&kvb[(size_t)(kc + kp) * (2 * DIM) + DIM + c4]);
            Vs[c4 + 0][kp] = __float2half_rn(vv4.x);
            Vs[c4 + 1][kp] = __float2half_rn(vv4.y);
            Vs[c4 + 2][kp] = __float2half_rn(vv4.z);
            Vs[c4 + 3][kp] = __float2half_rn(vv4.w);
        }
        __syncthreads();

        // S = Q K^T  (16 x 64 per warp)
        float S[8][4];
        #pragma unroll
        for (int j = 0; j < 8; j++)
            #pragma unroll
            for (int r = 0; r < 4; r++) S[j][r] = 0.f;
        #pragma unroll
        for (int c = 0; c < 8; c++) {
            #pragma unroll
            for (int j = 0; j < 8; j++) {
                float bf[2] = { Ks[j * 8 + g][c * 8 + t], Ks[j * 8 + g][c * 8 + 4 + t] };
                mma_tf32(S[j], qf[c], bf);
            }
        }
        // P = exp(clip(S)); rowsum
        #pragma unroll
        for (int j = 0; j < 8; j++) {
            #pragma unroll
            for (int r = 0; r < 4; r++) {
                float s = fminf(10.f, fmaxf(-10.f, S[j][r]));
                S[j][r] = __expf(s);
            }
            rs0 += S[j][0] + S[j][1];
            rs1 += S[j][2] + S[j][3];
        }
        // repack C-frags as fp16 A-frags (FMHA layout identity)
        unsigned af[4][4];
        #pragma unroll
        for (int kt = 0; kt < 4; kt++) {
            af[kt][0] = pack_h2(S[2 * kt][0], S[2 * kt][1]);
            af[kt][1] = pack_h2(S[2 * kt][2], S[2 * kt][3]);
            af[kt][2] = pack_h2(S[2 * kt + 1][0], S[2 * kt + 1][1]);
            af[kt][3] = pack_h2(S[2 * kt + 1][2], S[2 * kt + 1][3]);
        }
        // O += P @ V
        #pragma unroll
        for (int kt = 0; kt < 4; kt++) {
            #pragma unroll
            for (int dt = 0; dt < 8; dt++) {
                unsigned bf2[2];
                bf2[0] = *reinterpret_cast<const unsigned*>(&Vs[dt * 8 + g][kt * 16 + 2 * t]);
                bf2[1] = *reinterpret_cast<const unsigned*>(&Vs[dt * 8 + g][kt * 16 + 2 * t + 8]);
                mma_f16(o[dt], af[kt], bf2);
            }
        }
    }

    // rowsum across the quad (lanes sharing a row)
    rs0 += __shfl_xor_sync(0xffffffffu, rs0, 1);
    rs0 += __shfl_xor_sync(0xffffffffu, rs0, 2);
    rs1 += __shfl_xor_sync(0xffffffffu, rs1, 1);
    rs1 += __shfl_xor_sync(0xffffffffu, rs1, 2);
    const float i0 = 1.f / rs0, i1 = 1.f / rs1;

    float* ob = att + (size_t)b * NN * DIM + h * HD;
    #pragma unroll
    for (int dt = 0; dt < 8; dt++) {
        const int c0 = dt * 8 + 2 * t;
        *reinterpret_cast<float2*>(&ob[(size_t)r0 * DIM + c0]) =
            make_float2(o[dt][0] * i0, o[dt][1] * i0);
        *reinterpret_cast<float2*>(&ob[(size_t)(r0 + 8) * DIM + c0]) =
            make_float2(o[dt][2] * i1, o[dt][3] * i1);
    }
}

// ---------------- scalar: attn.mean() == 1/K exactly (softmax rows sum to 1) ----------------
__global__ void tail_kernel(float* out, int out_size) {
    if (out_size == BB * NN * DIM + 1) out[BB * NN * DIM] = 1.0f / (float)KK;
}

// ---------------- launch ----------------
extern "C" void kernel_launch(void* const* d_in, const int* in_sizes, int n_in,
                              void* d_out, int out_size) {
    const float* x      = (const float*)d_in[0];
    const float* ctx    = (const float*)d_in[1];
    const float* q_w    = (const float*)d_in[2];
    const float* q_b    = (const float*)d_in[3];
    const float* kv_w   = (const float*)d_in[4];
    const float* kv_b   = (const float*)d_in[5];
    const float* proj_w = (const float*)d_in[6];
    const float* proj_b = (const float*)d_in[7];
    float* out = (float*)d_out;

    float *ctxn = nullptr, *qs = nullptr, *kvs = nullptr, *atts = nullptr;
    cudaGetSymbolAddress((void**)&ctxn, g_ctxn);
    cudaGetSymbolAddress((void**)&qs,   g_q);
    cudaGetSymbolAddress((void**)&kvs,  g_kv);
    cudaGetSymbolAddress((void**)&atts, g_att);

    rmsnorm_kernel<<<BB * KK, 256>>>(ctx, ctxn);
    gemm_tf32<<<dim3(8, 64), 256>>>(x, q_w, q_b, qs, BB * NN, DIM, DIM, QSCALE);
    gemm_tf32<<<dim3(16, 64), 256>>>(ctxn, kv_w, kv_b, kvs, BB * KK, 2 * DIM, DIM, 1.0f);
    attn_kernel<<<dim3(16, 64), 256>>>(qs, kvs, atts);
    gemm_tf32<<<dim3(8, 64), 256>>>(atts, proj_w, proj_b, out, BB * NN, DIM, DIM, 1.0f);
    tail_kernel<<<1, 1>>>(out, out_size);
}

// round 2
// speedup vs baseline: 3.5745x; 3.5745x over previous
#include <cuda_runtime.h>
#include <cuda_fp16.h>
#include <cstdint>

#define NH 16
#define HD 64
#define DIM 1024
#define BB 4
#define NN 2048
#define KK 2048
#define QSCALE 0.125f

// ---------------- scratch (device globals: allocation-free) ----------------
__device__ __half g_xh  [(size_t)BB * NN * DIM];       // 16 MB
__device__ __half g_ctxn[(size_t)BB * KK * DIM];       // 16 MB
__device__ __half g_qh  [(size_t)BB * NN * DIM];       // 16 MB (pre-scaled)
__device__ __half g_kvh [(size_t)BB * KK * 2 * DIM];   // 32 MB
__device__ __half g_atth[(size_t)BB * NN * DIM];       // 16 MB
__device__ __half g_wq  [(size_t)DIM * DIM];
__device__ __half g_wkv [(size_t)DIM * 2 * DIM];
__device__ __half g_wp  [(size_t)DIM * DIM];

// ---------------- asm helpers ----------------
__device__ __forceinline__ uint32_t s2u(const void* p) {
    return (uint32_t)__cvta_generic_to_shared(p);
}
__device__ __forceinline__ void cp16(uint32_t dst, const void* src) {
    asm volatile("cp.async.ca.shared.global [%0], [%1], 16;\n" :: "r"(dst), "l"(src));
}
#define CP_COMMIT asm volatile("cp.async.commit_group;\n")
#define CP_WAIT(n) asm volatile("cp.async.wait_group %0;\n" :: "n"(n))

__device__ __forceinline__ void ldm_x4(unsigned r[4], uint32_t a) {
    asm volatile("ldmatrix.sync.aligned.m8n8.x4.shared.b16 {%0,%1,%2,%3}, [%4];"
                 : "=r"(r[0]), "=r"(r[1]), "=r"(r[2]), "=r"(r[3]) : "r"(a));
}
__device__ __forceinline__ void ldm_x4t(unsigned r[4], uint32_t a) {
    asm volatile("ldmatrix.sync.aligned.m8n8.x4.trans.shared.b16 {%0,%1,%2,%3}, [%4];"
                 : "=r"(r[0]), "=r"(r[1]), "=r"(r[2]), "=r"(r[3]) : "r"(a));
}
__device__ __forceinline__ void mma_f16(float c[4], const unsigned a[4], const unsigned b[2]) {
    asm volatile(
        "mma.sync.aligned.m16n8k16.row.col.f32.f16.f16.f32 "
        "{%0,%1,%2,%3},{%4,%5,%6,%7},{%8,%9},{%0,%1,%2,%3};\n"
        : "+f"(c[0]), "+f"(c[1]), "+f"(c[2]), "+f"(c[3])
        : "r"(a[0]), "r"(a[1]), "r"(a[2]), "r"(a[3]), "r"(b[0]), "r"(b[1]));
}
__device__ __forceinline__ unsigned pack_h2(float a, float b) {
    __half2 h = __floats2half2_rn(a, b);
    return *reinterpret_cast<unsigned*>(&h);
}

// ---------------- fp32 -> fp16 convert ----------------
__global__ void f2h_kernel(const float4* __restrict__ in, __half2* __restrict__ out, int n4) {
    int i = blockIdx.x * 256 + threadIdx.x;
    if (i < n4) {
        float4 v = in[i];
        out[2 * i]     = __floats2half2_rn(v.x, v.y);
        out[2 * i + 1] = __floats2half2_rn(v.z, v.w);
    }
}

// ---------------- rmsnorm -> fp16 ----------------
__global__ void rmsnorm_kernel(const float* __restrict__ in, __half* __restrict__ out) {
    const int row = blockIdx.x;
    const int tid = threadIdx.x;  // 256 threads x 4 floats
    const float4 v = reinterpret_cast<const float4*>(in + (size_t)row * DIM)[tid];
    float ss = v.x * v.x + v.y * v.y + v.z * v.z + v.w * v.w;
    #pragma unroll
    for (int o = 16; o; o >>= 1) ss += __shfl_xor_sync(0xffffffffu, ss, o);
    __shared__ float part[8];
    __shared__ float tot;
    if ((tid & 31) == 0) part[tid >> 5] = ss;
    __syncthreads();
    if (tid == 0) {
        float s = 0.f;
        #pragma unroll
        for (int i = 0; i < 8; i++) s += part[i];
        tot = s;
    }
    __syncthreads();
    const float r = rsqrtf(tot * (1.0f / DIM) + 1e-6f);
    __half2* ob = reinterpret_cast<__half2*>(out + (size_t)row * DIM);
    ob[2 * tid]     = __floats2half2_rn(v.x * r, v.y * r);
    ob[2 * tid + 1] = __floats2half2_rn(v.z * r, v.w * r);
}

// ---------------- fp16 GEMM: C = alpha*(A @ W + bias) ----------------
// A:[M,Kd] half row-major, W:[Kd,N] half row-major. Tile 128x128x32,
// 256 thr = 8 warps (2m x 4n), warp 64x32. cp.async double buffered.
#define ASTR 40
#define BSTR 136
template<bool HALF_OUT>
__global__ __launch_bounds__(256) void gemm_f16_kernel(
    const __half* __restrict__ A, const __half* __restrict__ W,
    const float* __restrict__ bias, void* __restrict__ Cv,
    int M, int N, int Kd, float alpha) {
    __shared__ __half As[2][128][ASTR];
    __shared__ __half Bs[2][32][BSTR];
    const int tid = threadIdx.x, lane = tid & 31, wid = tid >> 5;
    const int bm = blockIdx.y * 128, bn = blockIdx.x * 128;
    const int wm = (wid >> 2) * 64, wn = (wid & 3) * 32;

    float acc[4][4][4];
    #pragma unroll
    for (int i = 0; i < 4; i++)
        #pragma unroll
        for (int j = 0; j < 4; j++)
            #pragma unroll
            for (int r = 0; r < 4; r++) acc[i][j][r] = 0.f;

    const int a_r = tid >> 1, a_c = (tid & 1) * 16;
    const int b_r = tid >> 3, b_c = (tid & 7) * 16;
    const __half* Ag = A + (size_t)(bm + a_r) * Kd + a_c;
    const __half* Wg = W + (size_t)b_r * N + bn + b_c;

    auto issue = [&](int s, int k0) {
        uint32_t da = s2u(&As[s][a_r][a_c]);
        cp16(da, Ag + k0);
        cp16(da + 16, Ag + k0 + 8);
        uint32_t db = s2u(&Bs[s][b_r][b_c]);
        cp16(db, Wg + (size_t)k0 * N);
        cp16(db + 16, Wg + (size_t)k0 * N + 8);
    };

    const int lm_r = lane & 15, lm_c = (lane >> 4) * 8;
    const int NK = Kd / 32;
    issue(0, 0);
    CP_COMMIT;
    for (int kt = 0; kt < NK; kt++) {
        const int s = kt & 1;
        if (kt + 1 < NK) { issue(s ^ 1, (kt + 1) * 32); CP_COMMIT; CP_WAIT(1); }
        else             { CP_WAIT(0); }
        __syncthreads();
        #pragma unroll
        for (int kk = 0; kk < 32; kk += 16) {
            unsigned af[4][4], bf[2][4];
            #pragma unroll
            for (int mt = 0; mt < 4; mt++)
                ldm_x4(af[mt], s2u(&As[s][wm + mt * 16 + lm_r][kk + lm_c]));
            #pragma unroll
            for (int p = 0; p < 2; p++)
                ldm_x4t(bf[p], s2u(&Bs[s][kk + lm_r][wn + p * 16 + lm_c]));
            #pragma unroll
            for (int mt = 0; mt < 4; mt++)
                #pragma unroll
                for (int nt = 0; nt < 4; nt++)
                    mma_f16(acc[mt][nt], af[mt], &bf[nt >> 1][(nt & 1) * 2]);
        }
        __syncthreads();
    }

    #pragma unroll
    for (int mt = 0; mt < 4; mt++) {
        const int r0 = bm + wm + mt * 16 + (lane >> 2);
        #pragma unroll
        for (int nt = 0; nt < 4; nt++) {
            const int c0 = bn + wn + nt * 8 + 2 * (lane & 3);
            const float b0 = bias[c0], b1 = bias[c0 + 1];
            float v00 = alpha * (acc[mt][nt][0] + b0), v01 = alpha * (acc[mt][nt][1] + b1);
            float v10 = alpha * (acc[mt][nt][2] + b0), v11 = alpha * (acc[mt][nt][3] + b1);
            if (HALF_OUT) {
                __half* C = (__half*)Cv;
                *reinterpret_cast<__half2*>(&C[(size_t)r0 * N + c0]) = __floats2half2_rn(v00, v01);
                *reinterpret_cast<__half2*>(&C[(size_t)(r0 + 8) * N + c0]) = __floats2half2_rn(v10, v11);
            } else {
                float* C = (float*)Cv;
                *reinterpret_cast<float2*>(&C[(size_t)r0 * N + c0]) = make_float2(v00, v01);
                *reinterpret_cast<float2*>(&C[(size_t)(r0 + 8) * N + c0]) = make_float2(v10, v11);
            }
        }
    }
}

// ---------------- fused attention (fp16, clip bounds exp => no running max) ----------
// grid (N/128, B*H), 256 thr = 8 warps x 16 q-rows. 64-key tiles, cp.async double buf.
#define KVSTR 72
__global__ __launch_bounds__(256) void attn_f16_kernel(
    const __half* __restrict__ q, const __half* __restrict__ kv,
    __half* __restrict__ att) {
    __shared__ __half Ks[2][64][KVSTR];
    __shared__ __half Vs[2][64][KVSTR];
    const int tid = threadIdx.x, lane = tid & 31, wid = tid >> 5;
    const int bh = blockIdx.y, b = bh >> 4, h = bh & 15;
    const int row0 = blockIdx.x * 128 + wid * 16 + (lane >> 2);
    const __half* qb = q + (size_t)b * NN * DIM + h * HD;
    const __half* kvb = kv + (size_t)b * KK * 2 * DIM + h * HD;

    // resident Q fragments (m16k16 x 4 k-steps)
    unsigned qf[4][4];
    const int cq = 2 * (lane & 3);
    #pragma unroll
    for (int kt = 0; kt < 4; kt++) {
        qf[kt][0] = *reinterpret_cast<const unsigned*>(&qb[(size_t)row0 * DIM + kt * 16 + cq]);
        qf[kt][1] = *reinterpret_cast<const unsigned*>(&qb[(size_t)(row0 + 8) * DIM + kt * 16 + cq]);
        qf[kt][2] = *reinterpret_cast<const unsigned*>(&qb[(size_t)row0 * DIM + kt * 16 + 8 + cq]);
        qf[kt][3] = *reinterpret_cast<const unsigned*>(&qb[(size_t)(row0 + 8) * DIM + kt * 16 + 8 + cq]);
    }

    float o[8][4];
    #pragma unroll
    for (int i = 0; i < 8; i++)
        #pragma unroll
        for (int r = 0; r < 4; r++) o[i][r] = 0.f;
    float rs0 = 0.f, rs1 = 0.f;

    const int kr = tid >> 2, cc = (tid & 3) * 16;
    auto issue = [&](int s, int kc) {
        const __half* src = kvb + (size_t)(kc + kr) * (2 * DIM) + cc;
        uint32_t dk = s2u(&Ks[s][kr][cc]);
        cp16(dk, src);
        cp16(dk + 16, src + 8);
        uint32_t dv = s2u(&Vs[s][kr][cc]);
        cp16(dv, src + DIM);
        cp16(dv + 16, src + DIM + 8);
    };

    const int k_row = (lane & 7) + ((lane >> 4) << 3), k_col = ((lane >> 3) & 1) * 8;
    const int v_row = lane & 15, v_col = (lane >> 4) * 8;

    issue(0, 0);
    CP_COMMIT;
    const int NT = KK / 64;
    for (int it = 0; it < NT; it++) {
        const int s = it & 1;
        if (it + 1 < NT) { issue(s ^ 1, (it + 1) * 64); CP_COMMIT; CP_WAIT(1); }
        else             { CP_WAIT(0); }
        __syncthreads();

        // S = Q K^T  (16 x 64)
        float S[8][4];
        #pragma unroll
        for (int j = 0; j < 8; j++)
            #pragma unroll
            for (int r = 0; r < 4; r++) S[j][r] = 0.f;
        #pragma unroll
        for (int kt = 0; kt < 4; kt++) {
            unsigned kf[4][4];
            #pragma unroll
            for (int p = 0; p < 4; p++)
                ldm_x4(kf[p], s2u(&Ks[s][p * 16 + k_row][kt * 16 + k_col]));
            #pragma unroll
            for (int p = 0; p < 4; p++) {
                mma_f16(S[2 * p],     qf[kt], &kf[p][0]);
                mma_f16(S[2 * p + 1], qf[kt], &kf[p][2]);
            }
        }
        // P = exp(clip(S)); rowsums
        #pragma unroll
        for (int j = 0; j < 8; j++) {
            #pragma unroll
            for (int r = 0; r < 4; r++) {
                float sv = fminf(10.f, fmaxf(-10.f, S[j][r]));
                S[j][r] = __expf(sv);
            }
            rs0 += S[j][0] + S[j][1];
            rs1 += S[j][2] + S[j][3];
        }
        // repack C-frags -> fp16 A-frags
        unsigned af[4][4];
        #pragma unroll
        for (int kt = 0; kt < 4; kt++) {
            af[kt][0] = pack_h2(S[2 * kt][0], S[2 * kt][1]);
            af[kt][1] = pack_h2(S[2 * kt][2], S[2 * kt][3]);
            af[kt][2] = pack_h2(S[2 * kt + 1][0], S[2 * kt + 1][1]);
            af[kt][3] = pack_h2(S[2 * kt + 1][2], S[2 * kt + 1][3]);
        }
        // O += P @ V
        #pragma unroll
        for (int kt = 0; kt < 4; kt++) {
            #pragma unroll
            for (int p = 0; p < 4; p++) {
                unsigned vf[4];
                ldm_x4t(vf, s2u(&Vs[s][kt * 16 + v_row][p * 16 + v_col]));
                mma_f16(o[2 * p],     af[kt], &vf[0]);
                mma_f16(o[2 * p + 1], af[kt], &vf[2]);
            }
        }
        __syncthreads();
    }

    rs0 += __shfl_xor_sync(0xffffffffu, rs0, 1);
    rs0 += __shfl_xor_sync(0xffffffffu, rs0, 2);
    rs1 += __shfl_xor_sync(0xffffffffu, rs1, 1);
    rs1 += __shfl_xor_sync(0xffffffffu, rs1, 2);
    const float i0 = 1.f / rs0, i1 = 1.f / rs1;

    __half* ob = att + (size_t)b * NN * DIM + h * HD;
    #pragma unroll
    for (int dt = 0; dt < 8; dt++) {
        const int c0 = dt * 8 + 2 * (lane & 3);
        *reinterpret_cast<__half2*>(&ob[(size_t)row0 * DIM + c0]) =
            __floats2half2_rn(o[dt][0] * i0, o[dt][1] * i0);
        *reinterpret_cast<__half2*>(&ob[(size_t)(row0 + 8) * DIM + c0]) =
            __floats2half2_rn(o[dt][2] * i1, o[dt][3] * i1);
    }
}

// ---------------- attn.mean() == 1/K exactly ----------------
__global__ void tail_kernel(float* out, int out_size) {
    if (out_size == BB * NN * DIM + 1) out[BB * NN * DIM] = 1.0f / (float)KK;
}

// ---------------- launch ----------------
extern "C" void kernel_launch(void* const* d_in, const int* in_sizes, int n_in,
                              void* d_out, int out_size) {
    const float* x      = (const float*)d_in[0];
    const float* ctx    = (const float*)d_in[1];
    const float* q_w    = (const float*)d_in[2];
    const float* q_b    = (const float*)d_in[3];
    const float* kv_w   = (const float*)d_in[4];
    const float* kv_b   = (const float*)d_in[5];
    const float* proj_w = (const float*)d_in[6];
    const float* proj_b = (const float*)d_in[7];
    float* out = (float*)d_out;

    __half *xh, *ctxn, *qh, *kvh, *atth, *wq, *wkv, *wp;
    cudaGetSymbolAddress((void**)&xh,   g_xh);
    cudaGetSymbolAddress((void**)&ctxn, g_ctxn);
    cudaGetSymbolAddress((void**)&qh,   g_qh);
    cudaGetSymbolAddress((void**)&kvh,  g_kvh);
    cudaGetSymbolAddress((void**)&atth, g_atth);
    cudaGetSymbolAddress((void**)&wq,   g_wq);
    cudaGetSymbolAddress((void**)&wkv,  g_wkv);
    cudaGetSymbolAddress((void**)&wp,   g_wp);

    f2h_kernel<<<(BB * NN * DIM / 4 + 255) / 256, 256>>>((const float4*)x, (__half2*)xh, BB * NN * DIM / 4);
    f2h_kernel<<<(DIM * DIM / 4 + 255) / 256, 256>>>((const float4*)q_w, (__half2*)wq, DIM * DIM / 4);
    f2h_kernel<<<(DIM * 2 * DIM / 4 + 255) / 256, 256>>>((const float4*)kv_w, (__half2*)wkv, DIM * 2 * DIM / 4);
    f2h_kernel<<<(DIM * DIM / 4 + 255) / 256, 256>>>((const float4*)proj_w, (__half2*)wp, DIM * DIM / 4);
    rmsnorm_kernel<<<BB * KK, 256>>>(ctx, ctxn);

    gemm_f16_kernel<true><<<dim3(8, 64), 256>>>(xh, wq, q_b, qh, BB * NN, DIM, DIM, QSCALE);
    gemm_f16_kernel<true><<<dim3(16, 64), 256>>>(ctxn, wkv, kv_b, kvh, BB * KK, 2 * DIM, DIM, 1.0f);
    attn_f16_kernel<<<dim3(16, 64), 256>>>(qh, kvh, atth);
    gemm_f16_kernel<false><<<dim3(8, 64), 256>>>(atth, wp, proj_b, out, BB * NN, DIM, DIM, 1.0f);
    tail_kernel<<<1, 1>>>(out, out_size);
}